// round 2
// baseline (speedup 1.0000x reference)
#include <cuda_runtime.h>
#include <math_constants.h>

#define BB 4
#define SS 4096
#define WW 512
#define EE 64

// Scratch for projected Q, K, V (allocation-free rule: __device__ globals)
__device__ float g_Q[BB * SS * EE];
__device__ float g_K[BB * SS * EE];
__device__ float g_V[BB * SS * EE];

__device__ __forceinline__ float fast_exp2(float x) {
    float y;
    asm("ex2.approx.ftz.f32 %0, %1;" : "=f"(y) : "f"(x));
    return y;
}

// ---------------------------------------------------------------------------
// Kernel 1: fused QKV projection.
// grid = (16384/128, 3), block = 256.
// Each block computes a 128-row x 64-col tile of one of Q/K/V.
// Thread micro-tile: 8 rows x 4 cols (16 row-groups x 16 col-groups).
// ---------------------------------------------------------------------------
__global__ __launch_bounds__(256) void qkv_proj_kernel(
    const float* __restrict__ x,
    const float* __restrict__ Wq, const float* __restrict__ bq,
    const float* __restrict__ Wk, const float* __restrict__ bk,
    const float* __restrict__ Wv, const float* __restrict__ bv)
{
    const int mat = blockIdx.y;
    const float* Wm = (mat == 0) ? Wq : (mat == 1) ? Wk : Wv;
    const float* bm = (mat == 0) ? bq : (mat == 1) ? bk : bv;
    float* out = (mat == 0) ? g_Q : (mat == 1) ? g_K : g_V;

    const int row0 = blockIdx.x * 128;

    __shared__ float xs[32][132];  // xs[k][r], transposed x tile, padded
    __shared__ float ws[32][68];   // ws[k][c]

    const int tid = threadIdx.x;
    const int ty = tid >> 4;   // row group: rows 8*ty .. 8*ty+7
    const int tx = tid & 15;   // col group: cols 4*tx .. 4*tx+3

    float acc[8][4];
#pragma unroll
    for (int i = 0; i < 8; i++)
#pragma unroll
        for (int j = 0; j < 4; j++) acc[i][j] = 0.0f;

    for (int k0 = 0; k0 < WW; k0 += 32) {
        __syncthreads();
        // load x tile transposed: 128 rows x 32 k  (1024 float4 groups / 256 thr)
#pragma unroll
        for (int it = 0; it < 4; it++) {
            int i = tid + it * 256;
            int r = i >> 3;
            int c4 = (i & 7) * 4;
            float4 v = *(const float4*)&x[(size_t)(row0 + r) * WW + k0 + c4];
            xs[c4 + 0][r] = v.x;
            xs[c4 + 1][r] = v.y;
            xs[c4 + 2][r] = v.z;
            xs[c4 + 3][r] = v.w;
        }
        // load W tile: 32 k x 64 c  (512 float4 groups / 256 thr)
#pragma unroll
        for (int it = 0; it < 2; it++) {
            int i = tid + it * 256;
            int kk = i >> 4;
            int c4 = (i & 15) * 4;
            *(float4*)&ws[kk][c4] = *(const float4*)&Wm[(size_t)(k0 + kk) * EE + c4];
        }
        __syncthreads();

#pragma unroll 8
        for (int k = 0; k < 32; k++) {
            float4 b4 = *(float4*)&ws[k][4 * tx];
            float4 a0 = *(float4*)&xs[k][8 * ty];
            float4 a1 = *(float4*)&xs[k][8 * ty + 4];
            float a[8] = {a0.x, a0.y, a0.z, a0.w, a1.x, a1.y, a1.z, a1.w};
#pragma unroll
            for (int i = 0; i < 8; i++) {
                acc[i][0] = fmaf(a[i], b4.x, acc[i][0]);
                acc[i][1] = fmaf(a[i], b4.y, acc[i][1]);
                acc[i][2] = fmaf(a[i], b4.z, acc[i][2]);
                acc[i][3] = fmaf(a[i], b4.w, acc[i][3]);
            }
        }
    }

    const float4 bias = *(const float4*)&bm[4 * tx];
#pragma unroll
    for (int i = 0; i < 8; i++) {
        float4 o;
        o.x = acc[i][0] + bias.x;
        o.y = acc[i][1] + bias.y;
        o.z = acc[i][2] + bias.z;
        o.w = acc[i][3] + bias.w;
        *(float4*)&out[(size_t)(row0 + 8 * ty + i) * EE + 4 * tx] = o;
    }
}

// ---------------------------------------------------------------------------
// Kernel 2: flash attention, fp32.
// grid = (4096/64, 4), block = 256, dynamic smem = 4 * 64*68*4 bytes.
// Each block: 64 queries of one batch; loops over 64 tiles of 64 keys.
// Thread (ty,tx) owns S rows 4ty..4ty+3 / cols 4tx..4tx+3 and
// O rows 4ty..4ty+3 / dims 4tx..4tx+3. Online softmax in base-2.
// ---------------------------------------------------------------------------
#define LD 68  // padded smem row stride (floats), multiple of 4 for float4

__global__ __launch_bounds__(256) void attn_kernel(float* __restrict__ out)
{
    extern __shared__ float sm[];
    float* Qs = sm;                // [64][LD]  Qs[e][r]   (transposed, pre-scaled)
    float* Ks = Qs + 64 * LD;      // [64][LD]  Ks[e][c]   (transposed)
    float* Vs = Ks + 64 * LD;      // [64][LD]  Vs[j][d]
    float* Ps = Vs + 64 * LD;      // [64][LD]  Ps[j][r]   (transposed)

    const int b = blockIdx.y;
    const int q0 = blockIdx.x * 64;
    const float* Qg = g_Q + ((size_t)b * SS + q0) * EE;
    const float* Kg = g_K + (size_t)b * SS * EE;
    const float* Vg = g_V + (size_t)b * SS * EE;

    const int tid = threadIdx.x;
    const int ty = tid >> 4;
    const int tx = tid & 15;

    // load Q transposed, pre-scaled by (1/sqrt(E)) * log2(e) so softmax is pure 2^x
    const float qscale = 0.125f * 1.4426950408889634f;
#pragma unroll
    for (int it = 0; it < 4; it++) {
        int i = tid + it * 256;
        int r = i >> 4;
        int e4 = (i & 15) * 4;
        float4 v = *(const float4*)&Qg[(size_t)r * EE + e4];
        Qs[(e4 + 0) * LD + r] = v.x * qscale;
        Qs[(e4 + 1) * LD + r] = v.y * qscale;
        Qs[(e4 + 2) * LD + r] = v.z * qscale;
        Qs[(e4 + 3) * LD + r] = v.w * qscale;
    }

    float o[4][4];
#pragma unroll
    for (int i = 0; i < 4; i++)
#pragma unroll
        for (int j = 0; j < 4; j++) o[i][j] = 0.0f;
    float m[4], l[4];
#pragma unroll
    for (int i = 0; i < 4; i++) { m[i] = -1e30f; l[i] = 0.0f; }

    for (int kt = 0; kt < SS; kt += 64) {
        __syncthreads();  // previous PV done before overwriting Ks/Vs
        // load K tile transposed + V tile natural
#pragma unroll
        for (int it = 0; it < 4; it++) {
            int i = tid + it * 256;
            int r = i >> 4;
            int e4 = (i & 15) * 4;
            float4 v = *(const float4*)&Kg[(size_t)(kt + r) * EE + e4];
            Ks[(e4 + 0) * LD + r] = v.x;
            Ks[(e4 + 1) * LD + r] = v.y;
            Ks[(e4 + 2) * LD + r] = v.z;
            Ks[(e4 + 3) * LD + r] = v.w;
            float4 w = *(const float4*)&Vg[(size_t)(kt + r) * EE + e4];
            *(float4*)&Vs[r * LD + e4] = w;
        }
        __syncthreads();

        // S = (Q*scale*log2e) . K^T  -> base-2 logits
        float s[4][4];
#pragma unroll
        for (int i = 0; i < 4; i++)
#pragma unroll
            for (int j = 0; j < 4; j++) s[i][j] = 0.0f;

#pragma unroll 8
        for (int e = 0; e < 64; e++) {
            float4 q4 = *(float4*)&Qs[e * LD + 4 * ty];
            float4 k4 = *(float4*)&Ks[e * LD + 4 * tx];
            float qa[4] = {q4.x, q4.y, q4.z, q4.w};
            float kb[4] = {k4.x, k4.y, k4.z, k4.w};
#pragma unroll
            for (int i = 0; i < 4; i++)
#pragma unroll
                for (int j = 0; j < 4; j++)
                    s[i][j] = fmaf(qa[i], kb[j], s[i][j]);
        }

        // row max over this tile (reduce across the 16 tx-threads = low 16 lanes pattern)
        float rmax[4];
#pragma unroll
        for (int i = 0; i < 4; i++)
            rmax[i] = fmaxf(fmaxf(s[i][0], s[i][1]), fmaxf(s[i][2], s[i][3]));
#pragma unroll
        for (int off = 1; off < 16; off <<= 1)
#pragma unroll
            for (int i = 0; i < 4; i++)
                rmax[i] = fmaxf(rmax[i], __shfl_xor_sync(0xffffffffu, rmax[i], off));

        float alpha[4];
#pragma unroll
        for (int i = 0; i < 4; i++) {
            float mn = fmaxf(m[i], rmax[i]);
            alpha[i] = fast_exp2(m[i] - mn);
            m[i] = mn;
        }

        float rsum[4];
#pragma unroll
        for (int i = 0; i < 4; i++) {
            rsum[i] = 0.0f;
#pragma unroll
            for (int j = 0; j < 4; j++) {
                s[i][j] = fast_exp2(s[i][j] - m[i]);
                rsum[i] += s[i][j];
            }
        }
#pragma unroll
        for (int off = 1; off < 16; off <<= 1)
#pragma unroll
            for (int i = 0; i < 4; i++)
                rsum[i] += __shfl_xor_sync(0xffffffffu, rsum[i], off);

#pragma unroll
        for (int i = 0; i < 4; i++) {
            l[i] = l[i] * alpha[i] + rsum[i];
#pragma unroll
            for (int j = 0; j < 4; j++) o[i][j] *= alpha[i];
        }

        // write P transposed: Ps[key][row]
#pragma unroll
        for (int j = 0; j < 4; j++) {
            float4 p4 = make_float4(s[0][j], s[1][j], s[2][j], s[3][j]);
            *(float4*)&Ps[(4 * tx + j) * LD + 4 * ty] = p4;
        }
        __syncthreads();

        // O += P . V
#pragma unroll 8
        for (int j = 0; j < 64; j++) {
            float4 p4 = *(float4*)&Ps[j * LD + 4 * ty];
            float4 v4 = *(float4*)&Vs[j * LD + 4 * tx];
            float pa[4] = {p4.x, p4.y, p4.z, p4.w};
            float vb[4] = {v4.x, v4.y, v4.z, v4.w};
#pragma unroll
            for (int i = 0; i < 4; i++)
#pragma unroll
                for (int jj = 0; jj < 4; jj++)
                    o[i][jj] = fmaf(pa[i], vb[jj], o[i][jj]);
        }
    }

    // epilogue: normalize and store
    float* Og = out + ((size_t)b * SS + q0) * EE;
#pragma unroll
    for (int i = 0; i < 4; i++) {
        float inv = 1.0f / l[i];
        float4 r4 = make_float4(o[i][0] * inv, o[i][1] * inv, o[i][2] * inv, o[i][3] * inv);
        *(float4*)&Og[(size_t)(4 * ty + i) * EE + 4 * tx] = r4;
    }
}

// ---------------------------------------------------------------------------

extern "C" void kernel_launch(void* const* d_in, const int* in_sizes, int n_in,
                              void* d_out, int out_size)
{
    const float* x  = (const float*)d_in[0];
    const float* Wq = (const float*)d_in[1];
    const float* bq = (const float*)d_in[2];
    const float* Wk = (const float*)d_in[3];
    const float* bk = (const float*)d_in[4];
    const float* Wv = (const float*)d_in[5];
    const float* bv = (const float*)d_in[6];
    float* out = (float*)d_out;

    const int smem_bytes = 4 * 64 * LD * (int)sizeof(float);  // 69632
    cudaFuncSetAttribute(attn_kernel, cudaFuncAttributeMaxDynamicSharedMemorySize,
                         smem_bytes);

    dim3 pgrid(BB * SS / 128, 3);
    qkv_proj_kernel<<<pgrid, 256>>>(x, Wq, bq, Wk, bk, Wv, bv);

    dim3 agrid(SS / 64, BB);
    attn_kernel<<<agrid, 256, smem_bytes>>>(out);
}